// round 1
// baseline (speedup 1.0000x reference)
#include <cuda_runtime.h>
#include <cstdint>
#include <math.h>

#define BB 8
#define LL 2048
#define DD 256

// Scratch (allocation-free rule: __device__ globals)
__device__ __align__(16) float g_K[BB*LL*DD];
__device__ __align__(16) float g_V[BB*LL*DD];
__device__ __align__(16) float g_colsum[BB*LL];

__device__ __forceinline__ uint32_t f2tf32(float x){
  uint32_t u; asm("cvt.rna.tf32.f32 %0, %1;" : "=r"(u) : "f"(x)); return u;
}

#define BM 128
#define BN 128
#define BK 32
#define SK 36  // padded smem stride (conflict-free for frag loads)

// Generic tf32 NT GEMM: C[M,N] = A[M,K] @ B[N,K]^T  (BT=true: B given as [K,N] row-major)
// EPI 0: +bias, batch-remapped row store (QKV). EPI 1: exp(v/16). EPI 2: plain.
template<int EPI, bool BT>
__global__ __launch_bounds__(256) void gemm_tf32(
    const float* __restrict__ Ag, const float* __restrict__ Bg,
    float* __restrict__ Cg, const float* __restrict__ bias,
    int Kdim, int lda, int ldb, int ldc,
    long long aBS, long long bBS, long long cBS, long long outBS)
{
  __shared__ uint32_t As[BM][SK];
  __shared__ uint32_t Bs[BN][SK];

  const int z = blockIdx.z;
  const float* A = Ag + (size_t)z * aBS;
  const float* B = Bg + (size_t)z * bBS;
  float* C = Cg + (size_t)z * cBS;

  const int bm0 = blockIdx.y * BM;
  const int bn0 = blockIdx.x * BN;
  const int tid  = threadIdx.x;
  const int warp = tid >> 5;
  const int lane = tid & 31;
  const int g = lane >> 2, t = lane & 3;
  const int wm0 = (warp >> 2) * 64;   // 2 warps in M
  const int wn0 = (warp & 3) * 32;    // 4 warps in N

  float acc[4][4][4];
  #pragma unroll
  for (int i=0;i<4;i++)
    #pragma unroll
    for (int j=0;j<4;j++)
      #pragma unroll
      for (int f=0;f<4;f++) acc[i][j][f]=0.f;

  const int nk = Kdim / BK;
  for (int kt = 0; kt < nk; kt++) {
    // ---- load A tile (BMxBK), convert to tf32 ----
    #pragma unroll
    for (int i=0;i<4;i++){
      int s = tid + i*256;
      int r = s >> 3, c4 = (s & 7)*4;
      float4 v = *(const float4*)(A + (size_t)(bm0 + r)*lda + kt*BK + c4);
      As[r][c4+0]=f2tf32(v.x); As[r][c4+1]=f2tf32(v.y);
      As[r][c4+2]=f2tf32(v.z); As[r][c4+3]=f2tf32(v.w);
    }
    // ---- load B tile ----
    if (!BT) {
      #pragma unroll
      for (int i=0;i<4;i++){
        int s = tid + i*256;
        int r = s >> 3, c4 = (s & 7)*4;
        float4 v = *(const float4*)(B + (size_t)(bn0 + r)*ldb + kt*BK + c4);
        Bs[r][c4+0]=f2tf32(v.x); Bs[r][c4+1]=f2tf32(v.y);
        Bs[r][c4+2]=f2tf32(v.z); Bs[r][c4+3]=f2tf32(v.w);
      }
    } else {
      #pragma unroll
      for (int i=0;i<4;i++){
        int s = tid + i*256;
        int kk = s >> 5, c4 = (s & 31)*4;
        float4 v = *(const float4*)(B + (size_t)(kt*BK + kk)*ldb + bn0 + c4);
        Bs[c4+0][kk]=f2tf32(v.x); Bs[c4+1][kk]=f2tf32(v.y);
        Bs[c4+2][kk]=f2tf32(v.z); Bs[c4+3][kk]=f2tf32(v.w);
      }
    }
    __syncthreads();

    #pragma unroll
    for (int ks=0; ks<4; ks++){
      const int k0 = ks*8;
      uint32_t af[4][4], bf[4][2];
      #pragma unroll
      for (int mi=0;mi<4;mi++){
        int r = wm0 + mi*16;
        af[mi][0]=As[r+g  ][k0+t];   af[mi][1]=As[r+g+8][k0+t];
        af[mi][2]=As[r+g  ][k0+t+4]; af[mi][3]=As[r+g+8][k0+t+4];
      }
      #pragma unroll
      for (int ni=0;ni<4;ni++){
        int c = wn0 + ni*8;
        bf[ni][0]=Bs[c+g][k0+t]; bf[ni][1]=Bs[c+g][k0+t+4];
      }
      #pragma unroll
      for (int mi=0;mi<4;mi++)
        #pragma unroll
        for (int ni=0;ni<4;ni++)
          asm volatile("mma.sync.aligned.m16n8k8.row.col.f32.tf32.tf32.f32 "
            "{%0,%1,%2,%3}, {%4,%5,%6,%7}, {%8,%9}, {%0,%1,%2,%3};"
            : "+f"(acc[mi][ni][0]),"+f"(acc[mi][ni][1]),
              "+f"(acc[mi][ni][2]),"+f"(acc[mi][ni][3])
            : "r"(af[mi][0]),"r"(af[mi][1]),"r"(af[mi][2]),"r"(af[mi][3]),
              "r"(bf[ni][0]),"r"(bf[ni][1]));
    }
    __syncthreads();
  }

  // ---- epilogue ----
  #pragma unroll
  for (int mi=0;mi<4;mi++){
    #pragma unroll
    for (int ni=0;ni<4;ni++){
      int r = bm0 + wm0 + mi*16 + g;
      int c = bn0 + wn0 + ni*8 + 2*t;
      #pragma unroll
      for (int f=0; f<4; f++){
        int rr = r + ((f>=2) ? 8 : 0);
        int cc = c + (f & 1);
        float v = acc[mi][ni][f];
        if (EPI==0){
          size_t off = ((size_t)(rr>>11))*(size_t)outBS + (size_t)(rr & 2047)*ldc + cc;
          C[off] = v + bias[cc];
        } else if (EPI==1){
          C[(size_t)rr*ldc + cc] = expf(v * 0.0625f);   // scale = 1/sqrt(256)
        } else {
          C[(size_t)rr*ldc + cc] = v;
        }
      }
    }
  }
}

__global__ void zero_colsum_kernel(){
  int i = blockIdx.x*256 + threadIdx.x;
  g_colsum[i] = 0.f;
}

// column sums of P over q:  colsum[b][k] = sum_q P[b][q][k]
__global__ void colsum_kernel(const float* __restrict__ P){
  int k = blockIdx.x*256 + threadIdx.x;
  int b = blockIdx.z;
  const float* p = P + (size_t)b*LL*LL + (size_t)blockIdx.y*256*LL + k;
  float s = 0.f;
  #pragma unroll 8
  for (int q=0; q<256; q++) s += p[(size_t)q*LL];
  atomicAdd(&g_colsum[b*LL + k], s);
}

// in-place: A[b][q][k] = P[b][q][k] / colsum[b][k]
__global__ void norm_kernel(float* __restrict__ P){
  const size_t n4 = (size_t)BB*LL*LL/4;
  for (size_t i = blockIdx.x*(size_t)blockDim.x + threadIdx.x; i < n4;
       i += (size_t)gridDim.x*blockDim.x){
    size_t e = i*4;
    int b = (int)(e >> 22);          // / (L*L) = 2^22
    int k = (int)(e & (LL-1));       // % L (e is 4-aligned)
    float4 v  = ((float4*)P)[i];
    float4 cs = *(const float4*)&g_colsum[b*LL + k];
    v.x /= cs.x; v.y /= cs.y; v.z /= cs.z; v.w /= cs.w;
    ((float4*)P)[i] = v;
  }
}

extern "C" void kernel_launch(void* const* d_in, const int* in_sizes, int n_in,
                              void* d_out, int out_size)
{
  const float* x  = (const float*)d_in[0];
  const float* Wq = (const float*)d_in[1];
  const float* bq = (const float*)d_in[2];
  const float* Wk = (const float*)d_in[3];
  const float* bk = (const float*)d_in[4];
  const float* Wv = (const float*)d_in[5];
  const float* bv = (const float*)d_in[6];

  float* sp   = (float*)d_out;                       // S_p [B, 2L, D]
  float* Aout = sp + (size_t)BB*2*LL*DD;             // A   [B, L, L]

  float *gK, *gV;
  cudaGetSymbolAddress((void**)&gK, g_K);
  cudaGetSymbolAddress((void**)&gV, g_V);

  dim3 blk(256);
  const long long LD   = (long long)LL*DD;       // 524288
  const long long LD2  = 2LL*LL*DD;              // 1048576
  const long long LxL  = (long long)LL*LL;       // 4194304

  // 1) QKV projections: [16384,256] @ W^T + b  (M=16384 -> grid.y=128; N=256 -> grid.x=2)
  //    Q goes straight into S_p rows [0,L) per batch (outBS = 2*L*D); K,V to scratch (outBS = L*D -> contiguous).
  gemm_tf32<0,false><<<dim3(2,128,1), blk>>>(x, Wq, sp, bq, DD, DD, DD, DD, 0,0,0, LD2);
  gemm_tf32<0,false><<<dim3(2,128,1), blk>>>(x, Wk, gK, bk, DD, DD, DD, DD, 0,0,0, LD);
  gemm_tf32<0,false><<<dim3(2,128,1), blk>>>(x, Wv, gV, bv, DD, DD, DD, DD, 0,0,0, LD);

  // 2) P = exp((Q @ K^T)/16), per batch, unnormalized -> A region
  gemm_tf32<1,false><<<dim3(16,16,BB), blk>>>(sp, gK, Aout, nullptr,
      DD, DD, DD, LL, LD2, LD, LxL, 0);

  // 3) column sums over q
  zero_colsum_kernel<<<BB*LL/256, 256>>>();
  colsum_kernel<<<dim3(LL/256, 8, BB), 256>>>(Aout);

  // 4) normalize A in place
  norm_kernel<<<1184, 256>>>(Aout);

  // 5) C = A @ V -> S_p rows [L,2L) per batch  (BT: V is [K=L, N=256] row-major)
  gemm_tf32<2,true><<<dim3(2,16,BB), blk>>>(Aout, gV, sp + (size_t)LL*DD, nullptr,
      LL, LL, DD, DD, LxL, LD, LD2, 0);
}

// round 3
// speedup vs baseline: 1.4849x; 1.4849x over previous
#include <cuda_runtime.h>
#include <cstdint>
#include <math.h>

#define BB 8
#define LL 2048
#define DD 256

// Scratch (__device__ globals: allocation-free rule)
__device__ __align__(16) float g_X[BB*LL*DD];     // rounded x
__device__ __align__(16) float g_W[3*DD*DD];      // rounded Wq|Wk|Wv
__device__ __align__(16) float g_Q[BB*LL*DD];     // rounded Q+bias
__device__ __align__(16) float g_K[BB*LL*DD];     // rounded K+bias
__device__ __align__(16) float g_V[BB*LL*DD];     // rounded V+bias
__device__ __align__(16) float g_colsum[BB*LL];   // colsum -> inverted in place

__device__ __forceinline__ uint32_t f2tf32(float x){
  uint32_t u; asm("cvt.rna.tf32.f32 %0, %1;" : "=r"(u) : "f"(x)); return u;
}
__device__ __forceinline__ float rndf(float x){ return __uint_as_float(f2tf32(x)); }

__device__ __forceinline__ void cp16(uint32_t dst, const void* src){
  asm volatile("cp.async.cg.shared.global [%0], [%1], 16;\n" :: "r"(dst), "l"(src));
}
__device__ __forceinline__ void cpcommit(){ asm volatile("cp.async.commit_group;\n"); }
template<int N> __device__ __forceinline__ void cpwait(){
  asm volatile("cp.async.wait_group %0;\n" :: "n"(N));
}

#define MMA(a0,a1,a2,a3,b0,b1,c) \
  asm volatile("mma.sync.aligned.m16n8k8.row.col.f32.tf32.tf32.f32 " \
    "{%0,%1,%2,%3}, {%4,%5,%6,%7}, {%8,%9}, {%0,%1,%2,%3};" \
    : "+f"(c[0]),"+f"(c[1]),"+f"(c[2]),"+f"(c[3]) \
    : "r"(a0),"r"(a1),"r"(a2),"r"(a3),"r"(b0),"r"(b1))

// ============================================================
// round kernels
// ============================================================
__global__ void round_x_kernel(const float4* __restrict__ x){
  int i = blockIdx.x*256 + threadIdx.x;   // 1048576 float4
  float4 v = x[i];
  float4 o = { rndf(v.x), rndf(v.y), rndf(v.z), rndf(v.w) };
  ((float4*)g_X)[i] = o;
}
__global__ void round_w_kernel(const float4* __restrict__ Wq,
                               const float4* __restrict__ Wk,
                               const float4* __restrict__ Wv){
  int i = blockIdx.x*256 + threadIdx.x;   // 16384 float4 per W
  float4 a = Wq[i], b = Wk[i], c = Wv[i];
  float4 ra = { rndf(a.x),rndf(a.y),rndf(a.z),rndf(a.w) };
  float4 rb = { rndf(b.x),rndf(b.y),rndf(b.z),rndf(b.w) };
  float4 rc = { rndf(c.x),rndf(c.y),rndf(c.z),rndf(c.w) };
  ((float4*)g_W)[i]          = ra;
  ((float4*)g_W)[16384 + i]  = rb;
  ((float4*)g_W)[32768 + i]  = rc;
  if (i < 4096) ((float4*)g_colsum)[i] = make_float4(0.f,0.f,0.f,0.f);
}
__global__ void invcs_kernel(){
  int i = blockIdx.x*256 + threadIdx.x;   // 16384
  g_colsum[i] = 1.0f / g_colsum[i];
}

// ============================================================
// gemm128: BM=BN=128, BK=32, cp.async 2-stage, tf32 mma
// EPI 0: Q (+bias, store to sp rows, rounded copy to C2)
// EPI 1: P = exp(v/16), + fused colsum atomics
// EPI 2: K/V (+bias, rounded store)
// dyn smem: 2 stages * (128+128)*36 u32 = 73728 B
// ============================================================
template<int EPI>
__global__ __launch_bounds__(256,2) void gemm128(
    const float* __restrict__ Ag, const float* __restrict__ Bg,
    float* __restrict__ Cg, const float* __restrict__ bias,
    float* __restrict__ C2,
    int Kdim, int lda, int ldb, int ldc,
    long long aBS, long long bBS, long long cBS, long long outBS)
{
  extern __shared__ uint32_t sm[];
  const int z = blockIdx.z;
  const float* A = Ag + (size_t)z * aBS;
  const float* B = Bg + (size_t)z * bBS;
  float* C = Cg + (size_t)z * cBS;

  const int bm0 = blockIdx.y * 128;
  const int bn0 = blockIdx.x * 128;
  const int tid = threadIdx.x;
  const int warp = tid >> 5, lane = tid & 31;
  const int g = lane >> 2, t = lane & 3;
  const int wm0 = (warp >> 2) * 64;
  const int wn0 = (warp & 3) * 32;
  const uint32_t sb = (uint32_t)__cvta_generic_to_shared(sm);
  const int lr = tid >> 3, lc = (tid & 7) * 4;

  float acc[4][4][4];
  #pragma unroll
  for (int i=0;i<4;i++)
    #pragma unroll
    for (int j=0;j<4;j++)
      #pragma unroll
      for (int f=0;f<4;f++) acc[i][j][f]=0.f;

  const int nk = Kdim / 32;

  // stage s: As at s*4608, Bs at 9216 + s*4608 (u32 units)
  #define LOAD_TILES(kt, stg) { \
    _Pragma("unroll") \
    for (int i=0;i<4;i++){ \
      int r = lr + i*32; \
      cp16(sb + (((stg)*4608 + r*36 + lc)<<2), A + (size_t)(bm0+r)*lda + (kt)*32 + lc); \
    } \
    _Pragma("unroll") \
    for (int i=0;i<4;i++){ \
      int r = lr + i*32; \
      cp16(sb + ((9216 + (stg)*4608 + r*36 + lc)<<2), B + (size_t)(bn0+r)*ldb + (kt)*32 + lc); \
    } \
  }

  LOAD_TILES(0, 0); cpcommit();

  for (int kt = 0; kt < nk; kt++){
    const int stg = kt & 1;
    if (kt + 1 < nk){ LOAD_TILES(kt+1, stg^1); cpcommit(); cpwait<1>(); }
    else { cpwait<0>(); }
    __syncthreads();

    const uint32_t* As_ = sm + stg*4608;
    const uint32_t* Bs_ = sm + 9216 + stg*4608;
    #pragma unroll
    for (int ks=0; ks<4; ks++){
      const int k0 = ks*8;
      uint32_t af[4][4], bf[4][2];
      #pragma unroll
      for (int mi=0;mi<4;mi++){
        int r = wm0 + mi*16;
        af[mi][0]=As_[(r+g  )*36+k0+t];   af[mi][1]=As_[(r+g+8)*36+k0+t];
        af[mi][2]=As_[(r+g  )*36+k0+t+4]; af[mi][3]=As_[(r+g+8)*36+k0+t+4];
      }
      #pragma unroll
      for (int ni=0;ni<4;ni++){
        int c = wn0 + ni*8;
        bf[ni][0]=Bs_[(c+g)*36+k0+t]; bf[ni][1]=Bs_[(c+g)*36+k0+t+4];
      }
      #pragma unroll
      for (int mi=0;mi<4;mi++)
        #pragma unroll
        for (int ni=0;ni<4;ni++)
          MMA(af[mi][0],af[mi][1],af[mi][2],af[mi][3],bf[ni][0],bf[ni][1],acc[mi][ni]);
    }
    __syncthreads();
  }

  // ---- epilogue ----
  float csum[4][2];
  if (EPI==1){
    for (int ni=0;ni<4;ni++){ csum[ni][0]=0.f; csum[ni][1]=0.f; }
  }

  #pragma unroll
  for (int mi=0;mi<4;mi++){
    #pragma unroll
    for (int ni=0;ni<4;ni++){
      int r0 = bm0 + wm0 + mi*16 + g;
      int c  = bn0 + wn0 + ni*8 + 2*t;
      float v0=acc[mi][ni][0], v1=acc[mi][ni][1], v2=acc[mi][ni][2], v3=acc[mi][ni][3];
      if (EPI==0){
        float2 b2 = *(const float2*)(bias + c);
        v0+=b2.x; v1+=b2.y; v2+=b2.x; v3+=b2.y;
        int b0 = r0>>11,  m0 = r0&2047;
        int b1 = (r0+8)>>11, m1 = (r0+8)&2047;
        *(float2*)(C + (size_t)b0*outBS + (size_t)m0*ldc + c) = make_float2(v0,v1);
        *(float2*)(C + (size_t)b1*outBS + (size_t)m1*ldc + c) = make_float2(v2,v3);
        *(float2*)(C2 + (size_t)r0*256 + c)     = make_float2(rndf(v0),rndf(v1));
        *(float2*)(C2 + (size_t)(r0+8)*256 + c) = make_float2(rndf(v2),rndf(v3));
      } else if (EPI==2){
        float2 b2 = *(const float2*)(bias + c);
        *(float2*)(C + (size_t)r0*ldc + c)     = make_float2(rndf(v0+b2.x),rndf(v1+b2.y));
        *(float2*)(C + (size_t)(r0+8)*ldc + c) = make_float2(rndf(v2+b2.x),rndf(v3+b2.y));
      } else { // EPI==1
        float e0=expf(v0*0.0625f), e1=expf(v1*0.0625f);
        float e2=expf(v2*0.0625f), e3=expf(v3*0.0625f);
        *(float2*)(C + (size_t)r0*ldc + c)     = make_float2(e0,e1);
        *(float2*)(C + (size_t)(r0+8)*ldc + c) = make_float2(e2,e3);
        csum[ni][0] += e0+e2; csum[ni][1] += e1+e3;
      }
    }
  }

  if (EPI==1){
    float* sCol = (float*)sm;     // reuse (all compute done after last sync)
    __syncthreads();
    if (tid < 128) sCol[tid] = 0.f;
    __syncthreads();
    #pragma unroll
    for (int ni=0;ni<4;ni++){
      atomicAdd(&sCol[wn0 + ni*8 + 2*t    ], csum[ni][0]);
      atomicAdd(&sCol[wn0 + ni*8 + 2*t + 1], csum[ni][1]);
    }
    __syncthreads();
    if (tid < 128) atomicAdd(&g_colsum[z*LL + bn0 + tid], sCol[tid]);
  }
  #undef LOAD_TILES
}

// ============================================================
// gemm_av: C = (P/colsum) @ V.  BM=64, BN=256, BK=32.
// A path: LDG + fused normalize (multiply by inv colsum) + writeback + tf32.
// B path: cp.async of pre-rounded V, raw [k][d] layout.
// dyn smem: As 2*64*36 + Bs 2*32*260 u32 = 84992 B
// ============================================================
__global__ __launch_bounds__(256,2) void gemm_av(
    float* __restrict__ P,        // A region [B][L][L], normalized in place
    const float* __restrict__ V,  // g_V rounded [B][L][D]
    float* __restrict__ Cg)       // sp + L*D
{
  extern __shared__ uint32_t sm[];
  const int z = blockIdx.z;
  float* A = P + (size_t)z*LL*LL;
  const float* B = V + (size_t)z*LL*DD;
  float* C = Cg + (size_t)z*(2LL*LL*DD);
  const float* inv = g_colsum + z*LL;

  const int bm0 = blockIdx.y * 64;
  const int tid = threadIdx.x;
  const int warp = tid >> 5, lane = tid & 31;
  const int g = lane >> 2, t = lane & 3;
  const int wm0 = (warp >> 2) * 32;
  const int wn0 = (warp & 3) * 64;
  const uint32_t sb = (uint32_t)__cvta_generic_to_shared(sm);
  const int lr = tid >> 3, lc = (tid & 7) * 4;

  float acc[2][8][4];
  #pragma unroll
  for (int i=0;i<2;i++)
    #pragma unroll
    for (int j=0;j<8;j++)
      #pragma unroll
      for (int f=0;f<4;f++) acc[i][j][f]=0.f;

  uint32_t areg[8];

  // process tile kt of A: normalize, write back, convert to tf32 regs
  #define PROC_A(kt) { \
    float4 iv = *(const float4*)(inv + (kt)*32 + lc); \
    _Pragma("unroll") \
    for (int i=0;i<2;i++){ \
      float* ap = A + (size_t)(bm0 + lr + i*32)*LL + (kt)*32 + lc; \
      float4 p = *(const float4*)ap; \
      p.x*=iv.x; p.y*=iv.y; p.z*=iv.z; p.w*=iv.w; \
      *(float4*)ap = p; \
      areg[i*4+0]=f2tf32(p.x); areg[i*4+1]=f2tf32(p.y); \
      areg[i*4+2]=f2tf32(p.z); areg[i*4+3]=f2tf32(p.w); \
    } \
  }
  #define LOAD_B(kt, stg) { \
    _Pragma("unroll") \
    for (int i=0;i<8;i++){ \
      int s = tid + i*256; int kk = s>>6; int ch=(s&63)*4; \
      cp16(sb + ((4608 + (stg)*8320 + kk*260 + ch)<<2), B + (size_t)((kt)*32+kk)*DD + ch); \
    } \
  }

  PROC_A(0);
  LOAD_B(0, 0); cpcommit();

  const int nk = LL/32;   // 64
  for (int kt = 0; kt < nk; kt++){
    const int stg = kt & 1;
    // store processed A tile kt
    #pragma unroll
    for (int i=0;i<2;i++){
      uint32_t* d = sm + stg*2304 + (lr + i*32)*36 + lc;
      *(uint4*)d = make_uint4(areg[i*4],areg[i*4+1],areg[i*4+2],areg[i*4+3]);
    }
    const bool more = (kt + 1 < nk);
    float4 rawp[2]; float4 iv;
    if (more){
      LOAD_B(kt+1, stg^1); cpcommit();
      iv = *(const float4*)(inv + (kt+1)*32 + lc);
      #pragma unroll
      for (int i=0;i<2;i++)
        rawp[i] = *(const float4*)(A + (size_t)(bm0 + lr + i*32)*LL + (kt+1)*32 + lc);
      cpwait<1>();
    } else {
      cpwait<0>();
    }
    __syncthreads();

    const uint32_t* As_ = sm + stg*2304;
    const uint32_t* Bs_ = sm + 4608 + stg*8320;
    #pragma unroll
    for (int ks=0; ks<4; ks++){
      const int k0 = ks*8;
      uint32_t af[2][4], bf[8][2];
      #pragma unroll
      for (int mi=0;mi<2;mi++){
        int r = wm0 + mi*16;
        af[mi][0]=As_[(r+g  )*36+k0+t];   af[mi][1]=As_[(r+g+8)*36+k0+t];
        af[mi][2]=As_[(r+g  )*36+k0+t+4]; af[mi][3]=As_[(r+g+8)*36+k0+t+4];
      }
      #pragma unroll
      for (int ni=0;ni<8;ni++){
        int c = wn0 + ni*8;
        bf[ni][0]=Bs_[(k0+t  )*260 + c+g];
        bf[ni][1]=Bs_[(k0+t+4)*260 + c+g];
      }
      #pragma unroll
      for (int mi=0;mi<2;mi++)
        #pragma unroll
        for (int ni=0;ni<8;ni++)
          MMA(af[mi][0],af[mi][1],af[mi][2],af[mi][3],bf[ni][0],bf[ni][1],acc[mi][ni]);
    }

    if (more){
      #pragma unroll
      for (int i=0;i<2;i++){
        float4 p = rawp[i];
        p.x*=iv.x; p.y*=iv.y; p.z*=iv.z; p.w*=iv.w;
        *(float4*)(A + (size_t)(bm0 + lr + i*32)*LL + (kt+1)*32 + lc) = p;
        areg[i*4+0]=f2tf32(p.x); areg[i*4+1]=f2tf32(p.y);
        areg[i*4+2]=f2tf32(p.z); areg[i*4+3]=f2tf32(p.w);
      }
    }
    __syncthreads();
  }

  #pragma unroll
  for (int mi=0;mi<2;mi++){
    #pragma unroll
    for (int ni=0;ni<8;ni++){
      int r = bm0 + wm0 + mi*16 + g;
      int c = wn0 + ni*8 + 2*t;
      *(float2*)(C + (size_t)r*DD + c)     = make_float2(acc[mi][ni][0],acc[mi][ni][1]);
      *(float2*)(C + (size_t)(r+8)*DD + c) = make_float2(acc[mi][ni][2],acc[mi][ni][3]);
    }
  }
  #undef PROC_A
  #undef LOAD_B
}

// ============================================================
extern "C" void kernel_launch(void* const* d_in, const int* in_sizes, int n_in,
                              void* d_out, int out_size)
{
  const float* x  = (const float*)d_in[0];
  const float* Wq = (const float*)d_in[1];
  const float* bq = (const float*)d_in[2];
  const float* Wk = (const float*)d_in[3];
  const float* bk = (const float*)d_in[4];
  const float* Wv = (const float*)d_in[5];
  const float* bv = (const float*)d_in[6];

  float* sp   = (float*)d_out;                  // S_p [B, 2L, D]
  float* Aout = sp + (size_t)BB*2*LL*DD;        // A   [B, L, L]

  float *gX,*gW,*gQ,*gK,*gV;
  cudaGetSymbolAddress((void**)&gX, g_X);
  cudaGetSymbolAddress((void**)&gW, g_W);
  cudaGetSymbolAddress((void**)&gQ, g_Q);
  cudaGetSymbolAddress((void**)&gK, g_K);
  cudaGetSymbolAddress((void**)&gV, g_V);

  const int SM128 = 73728, SMAV = 84992;
  cudaFuncSetAttribute(gemm128<0>, cudaFuncAttributeMaxDynamicSharedMemorySize, SM128);
  cudaFuncSetAttribute(gemm128<1>, cudaFuncAttributeMaxDynamicSharedMemorySize, SM128);
  cudaFuncSetAttribute(gemm128<2>, cudaFuncAttributeMaxDynamicSharedMemorySize, SM128);
  cudaFuncSetAttribute(gemm_av,    cudaFuncAttributeMaxDynamicSharedMemorySize, SMAV);

  const long long LD  = (long long)LL*DD;
  const long long LD2 = 2LL*LL*DD;
  const long long LxL = (long long)LL*LL;

  round_x_kernel<<<4096, 256>>>((const float4*)x);
  round_w_kernel<<<64, 256>>>((const float4*)Wq,(const float4*)Wk,(const float4*)Wv);

  // QKV projections from rounded x/W
  gemm128<0><<<dim3(2,128,1), 256, SM128>>>(gX, gW,          sp, bq, gQ, DD,DD,DD,DD, 0,0,0, LD2);
  gemm128<2><<<dim3(2,128,1), 256, SM128>>>(gX, gW+  DD*DD,  gK, bk, nullptr, DD,DD,DD,DD, 0,0,0, 0);
  gemm128<2><<<dim3(2,128,1), 256, SM128>>>(gX, gW+2*DD*DD,  gV, bv, nullptr, DD,DD,DD,DD, 0,0,0, 0);

  // P = exp(Q K^T / 16), unnormalized, + fused column sums
  gemm128<1><<<dim3(16,16,BB), 256, SM128>>>(gQ, gK, Aout, nullptr, nullptr,
      DD, DD, DD, LL, LD, LD, LxL, 0);

  invcs_kernel<<<64, 256>>>();

  // C = (P/colsum) @ V  with fused in-place normalization of A
  gemm_av<<<dim3(1,32,BB), 256, SMAV>>>(Aout, gV, sp + (size_t)LL*DD);
}